// round 6
// baseline (speedup 1.0000x reference)
#include <cuda_runtime.h>

// ICFM v5: v4 + L2 prefetch of next batch's vec rows + occupancy nudge.
// v4 was DRAM-latency exposed (DRAM 63%, occ 47%): warps don't keep enough
// bytes in flight to cover 577-cyc DRAM latency. The next batch's feat
// indices (fn) are already resident a full iteration early, so each lane
// issues one prefetch.global.L2 for one 128B line of the next batch's rows
// (32 lanes == 32 lines == 8 interactions x 2 feats x 2 halves). Next
// iteration's blocking LDGs then see ~L2 latency instead of DRAM latency.

#define NSEG 16384
#define UNROLL 4   // slots; interactions per warp-batch = 2*UNROLL = 8

__global__ void icfm_zero(float* __restrict__ out) {
    int i = blockIdx.x * blockDim.x + threadIdx.x;
    if (i < NSEG) out[i] = 0.0f;
}

__global__ void __launch_bounds__(256, 5) icfm_main(
    const int*    __restrict__ intr_idxs,
    const float*  __restrict__ intr_divs,
    const int2*   __restrict__ feat_idxs,
    const int*    __restrict__ seg_ids,
    const float4* __restrict__ vecs,     // [N_FEATS, 16] as float4
    const float*  __restrict__ intr_W,
    const float*  __restrict__ intr_b,
    float*        __restrict__ out,
    int T)
{
    const int lane  = threadIdx.x & 31;
    const int group = lane >> 4;      // which interaction of a slot-pair
    const int sub   = lane & 15;      // position within the 256B row
    const int oct   = lane & 7;       // interaction-in-batch this lane owns

    const int warp_global = (blockIdx.x * blockDim.x + threadIdx.x) >> 5;
    const int nwarps      = (gridDim.x * blockDim.x) >> 5;
    const int nbatches    = (T + 2 * UNROLL - 1) / (2 * UNROLL);

    const float bias = __ldg(&intr_b[0]);

    int batch = warp_global;
    if (batch >= nbatches) return;

    // Prologue: feat indices for the first batch (clamped).
    int2 fc[UNROLL];
    {
        const int base = batch * (2 * UNROLL);
        #pragma unroll
        for (int it = 0; it < UNROLL; it++) {
            int j = base + it * 2 + group;
            fc[it] = __ldg(&feat_idxs[j < T ? j : T - 1]);
        }
    }

    while (batch < nbatches) {
        const int base = batch * (2 * UNROLL);
        const int nb   = batch + nwarps;

        // 8 independent row gathers (MLP=8); rows were L2-prefetched last iter.
        float4 a[UNROLL], b[UNROLL];
        #pragma unroll
        for (int it = 0; it < UNROLL; it++) {
            a[it] = __ldg(&vecs[(long long)fc[it].x * 16 + sub]);
            b[it] = __ldg(&vecs[(long long)fc[it].y * 16 + sub]);
        }

        // Lane-parallel scalar loads for this batch.
        const int  j2     = base + oct;
        const bool valid2 = j2 < T;
        const int  j2c    = valid2 ? j2 : T - 1;
        const int  idx    = __ldg(&intr_idxs[j2c]);
        const float dv    = __ldg(&intr_divs[j2c]);
        const int  sg     = __ldg(&seg_ids[j2c]);
        const float w     = __ldg(&intr_W[idx]);
        const float coef  = __fdividef(w, dv);

        // Next batch's feat indices + L2 prefetch of its 32 row-halves.
        int2 fn[UNROLL];
        if (nb < nbatches) {
            const int nbase = nb * (2 * UNROLL);
            #pragma unroll
            for (int it = 0; it < UNROLL; it++) {
                int j = nbase + it * 2 + group;
                fn[it] = __ldg(&feat_idxs[j < T ? j : T - 1]);
            }
            // Per-group: 16 lanes cover 4 slots x 2 feats x 2 halves = 16 lines.
            const int it2   = sub & 3;
            const int featf = (sub >> 2) & 1;
            const int half  = (sub >> 3) & 1;
            int2 fsel = fn[0];
            if (it2 == 1) fsel = fn[1];
            if (it2 == 2) fsel = fn[2];
            if (it2 == 3) fsel = fn[3];
            const int row = featf ? fsel.y : fsel.x;
            const float4* paddr = &vecs[(long long)row * 16 + half * 8];
            asm volatile("prefetch.global.L2 [%0];" :: "l"(paddr));
        }

        // Dot products + 16-lane reductions; route sums to owning lanes.
        float v = 0.0f;
        #pragma unroll
        for (int it = 0; it < UNROLL; it++) {
            float p = a[it].x * b[it].x + a[it].y * b[it].y
                    + a[it].z * b[it].z + a[it].w * b[it].w;
            p += __shfl_xor_sync(0xffffffffu, p, 8);
            p += __shfl_xor_sync(0xffffffffu, p, 4);
            p += __shfl_xor_sync(0xffffffffu, p, 2);
            p += __shfl_xor_sync(0xffffffffu, p, 1);
            const float q  = __shfl_xor_sync(0xffffffffu, p, 16);
            const float g0 = (lane < 16) ? p : q;
            const float g1 = (lane < 16) ? q : p;
            if ((lane & 6) == 2 * it)
                v = (lane & 1) ? g1 : g0;
        }
        v = valid2 ? (coef * v + bias) : 0.0f;

        // Segment-aggregated accumulate: one atomic when batch is uniform.
        const int      sg0 = __shfl_sync(0xffffffffu, sg, 0);
        const unsigned uni = __ballot_sync(0xffffffffu, sg == sg0);
        if (uni == 0xffffffffu) {
            v += __shfl_xor_sync(0xffffffffu, v, 4);
            v += __shfl_xor_sync(0xffffffffu, v, 2);
            v += __shfl_xor_sync(0xffffffffu, v, 1);
            if (lane == 0) atomicAdd(&out[sg0], v);
        } else {
            if (lane < 8) atomicAdd(&out[sg], v);
        }

        #pragma unroll
        for (int it = 0; it < UNROLL; it++) fc[it] = fn[it];
        batch = nb;
    }
}

extern "C" void kernel_launch(void* const* d_in, const int* in_sizes, int n_in,
                              void* d_out, int out_size) {
    const int*    intr_idxs = (const int*)   d_in[0];
    const float*  intr_divs = (const float*) d_in[1];
    const int2*   feat_idxs = (const int2*)  d_in[2];
    const int*    seg_ids   = (const int*)   d_in[3];
    const float4* vecs      = (const float4*)d_in[4];
    const float*  intr_W    = (const float*) d_in[5];
    const float*  intr_b    = (const float*) d_in[6];
    float*        out       = (float*)d_out;

    const int T = in_sizes[0];

    icfm_zero<<<(NSEG + 255) / 256, 256>>>(out);

    const int blocks = 148 * 5;  // persistent-ish, matches launch_bounds occ
    icfm_main<<<blocks, 256>>>(intr_idxs, intr_divs, feat_idxs, seg_ids,
                               vecs, intr_W, intr_b, out, T);
}

// round 7
// speedup vs baseline: 1.0286x; 1.0286x over previous
#include <cuda_runtime.h>

// ICFM v6: v4 dataflow (best known, 54us) + 5-CTA/SM occupancy cap.
// v5's L2 prefetch REGRESSED (54->70us): prefetch.global.L2 costs a full LTS
// transaction, doubling L2 traffic (47->63%) on an L2-bound path. Reverted.
// v5 did prove this structure fits in 48 regs under __launch_bounds__(256,5),
// so keep that: occ 47->~59%, raising stall-time in-flight bytes ~25%.

#define NSEG 16384
#define UNROLL 4   // slots; interactions per warp-batch = 2*UNROLL = 8

__global__ void icfm_zero(float* __restrict__ out) {
    int i = blockIdx.x * blockDim.x + threadIdx.x;
    if (i < NSEG) out[i] = 0.0f;
}

__global__ void __launch_bounds__(256, 5) icfm_main(
    const int*    __restrict__ intr_idxs,
    const float*  __restrict__ intr_divs,
    const int2*   __restrict__ feat_idxs,
    const int*    __restrict__ seg_ids,
    const float4* __restrict__ vecs,     // [N_FEATS, 16] as float4
    const float*  __restrict__ intr_W,
    const float*  __restrict__ intr_b,
    float*        __restrict__ out,
    int T)
{
    const int lane  = threadIdx.x & 31;
    const int group = lane >> 4;      // which interaction of a slot-pair
    const int sub   = lane & 15;      // position within the 256B row
    const int oct   = lane & 7;       // interaction-in-batch this lane owns

    const int warp_global = (blockIdx.x * blockDim.x + threadIdx.x) >> 5;
    const int nwarps      = (gridDim.x * blockDim.x) >> 5;
    const int nbatches    = (T + 2 * UNROLL - 1) / (2 * UNROLL);

    const float bias = __ldg(&intr_b[0]);

    int batch = warp_global;
    if (batch >= nbatches) return;

    // Prologue: feat indices for the first batch (clamped).
    int2 fc[UNROLL];
    {
        const int base = batch * (2 * UNROLL);
        #pragma unroll
        for (int it = 0; it < UNROLL; it++) {
            int j = base + it * 2 + group;
            fc[it] = __ldg(&feat_idxs[j < T ? j : T - 1]);
        }
    }

    while (batch < nbatches) {
        const int base = batch * (2 * UNROLL);
        const int nb   = batch + nwarps;

        // 8 independent row gathers (MLP=8), issued first.
        float4 a[UNROLL], b[UNROLL];
        #pragma unroll
        for (int it = 0; it < UNROLL; it++) {
            a[it] = __ldg(&vecs[(long long)fc[it].x * 16 + sub]);
            b[it] = __ldg(&vecs[(long long)fc[it].y * 16 + sub]);
        }

        // Lane-parallel scalar loads for this batch (overlap the gather wait).
        const int  j2     = base + oct;
        const bool valid2 = j2 < T;
        const int  j2c    = valid2 ? j2 : T - 1;
        const int  idx    = __ldg(&intr_idxs[j2c]);
        const float dv    = __ldg(&intr_divs[j2c]);
        const int  sg     = __ldg(&seg_ids[j2c]);
        const float w     = __ldg(&intr_W[idx]);
        const float coef  = __fdividef(w, dv);

        // Prefetch next batch's feat indices (registers only — no L2 prefetch).
        int2 fn[UNROLL];
        if (nb < nbatches) {
            const int nbase = nb * (2 * UNROLL);
            #pragma unroll
            for (int it = 0; it < UNROLL; it++) {
                int j = nbase + it * 2 + group;
                fn[it] = __ldg(&feat_idxs[j < T ? j : T - 1]);
            }
        }

        // Dot products + 16-lane reductions; route sums to owning lanes.
        float v = 0.0f;
        #pragma unroll
        for (int it = 0; it < UNROLL; it++) {
            float p = a[it].x * b[it].x + a[it].y * b[it].y
                    + a[it].z * b[it].z + a[it].w * b[it].w;
            p += __shfl_xor_sync(0xffffffffu, p, 8);
            p += __shfl_xor_sync(0xffffffffu, p, 4);
            p += __shfl_xor_sync(0xffffffffu, p, 2);
            p += __shfl_xor_sync(0xffffffffu, p, 1);
            const float q  = __shfl_xor_sync(0xffffffffu, p, 16);
            const float g0 = (lane < 16) ? p : q;
            const float g1 = (lane < 16) ? q : p;
            if ((lane & 6) == 2 * it)
                v = (lane & 1) ? g1 : g0;
        }
        v = valid2 ? (coef * v + bias) : 0.0f;

        // Segment-aggregated accumulate: one atomic when the batch is uniform.
        const int      sg0 = __shfl_sync(0xffffffffu, sg, 0);
        const unsigned uni = __ballot_sync(0xffffffffu, sg == sg0);
        if (uni == 0xffffffffu) {
            v += __shfl_xor_sync(0xffffffffu, v, 4);
            v += __shfl_xor_sync(0xffffffffu, v, 2);
            v += __shfl_xor_sync(0xffffffffu, v, 1);
            if (lane == 0) atomicAdd(&out[sg0], v);
        } else {
            if (lane < 8) atomicAdd(&out[sg], v);
        }

        #pragma unroll
        for (int it = 0; it < UNROLL; it++) fc[it] = fn[it];
        batch = nb;
    }
}

extern "C" void kernel_launch(void* const* d_in, const int* in_sizes, int n_in,
                              void* d_out, int out_size) {
    const int*    intr_idxs = (const int*)   d_in[0];
    const float*  intr_divs = (const float*) d_in[1];
    const int2*   feat_idxs = (const int2*)  d_in[2];
    const int*    seg_ids   = (const int*)   d_in[3];
    const float4* vecs      = (const float4*)d_in[4];
    const float*  intr_W    = (const float*) d_in[5];
    const float*  intr_b    = (const float*) d_in[6];
    float*        out       = (float*)d_out;

    const int T = in_sizes[0];

    icfm_zero<<<(NSEG + 255) / 256, 256>>>(out);

    const int blocks = 148 * 5;  // persistent-ish, matches launch_bounds occ
    icfm_main<<<blocks, 256>>>(intr_idxs, intr_divs, feat_idxs, seg_ids,
                               vecs, intr_W, intr_b, out, T);
}